// round 10
// baseline (speedup 1.0000x reference)
#include <cuda_runtime.h>
#include <cuda_bf16.h>
#include <math.h>
#include <stdint.h>

#define B_   8
#define P_   128
#define N_   256
#define D_   128
#define M_   (B_*P_*N_)        // 262144 rows

// ---------------- scratch (device globals; no allocation allowed) ----------------
__device__ __align__(16) __nv_bfloat16 g_a_hi[(size_t)M_ * 256];
__device__ __align__(16) __nv_bfloat16 g_a_lo[(size_t)M_ * 256];
__device__ float g_q[(size_t)M_ * D_];
__device__ float g_k[(size_t)M_ * D_];
__device__ float g_v[(size_t)M_ * D_];
__device__ __align__(16) __nv_bfloat16 g_att_hi[(size_t)M_ * D_];
__device__ __align__(16) __nv_bfloat16 g_att_lo[(size_t)M_ * D_];
// weights transposed to [n][k], bf16-split. layout: Wq(32768) Wk Wv W1(16384) W2
__device__ __align__(16) __nv_bfloat16 g_wh[131072];
__device__ __align__(16) __nv_bfloat16 g_wl[131072];

// ---------------- helpers ----------------
__device__ __forceinline__ uint32_t smem_u32(const void* p) {
    uint32_t a;
    asm("{ .reg .u64 t; cvta.to.shared.u64 t, %1; cvt.u32.u64 %0, t; }" : "=r"(a) : "l"(p));
    return a;
}
__device__ __forceinline__ void split_bf16(float x, uint16_t& h, uint16_t& l) {
    __nv_bfloat16 hb = __float2bfloat16(x);
    __nv_bfloat16 lb = __float2bfloat16(x - __bfloat162float(hb));
    h = __bfloat16_as_ushort(hb);
    l = __bfloat16_as_ushort(lb);
}
__device__ __forceinline__ void split2(float a, float b, uint32_t& hi, uint32_t& lo) {
    uint16_t ha, la, hb, lb;
    split_bf16(a, ha, la);
    split_bf16(b, hb, lb);
    hi = (uint32_t)ha | ((uint32_t)hb << 16);
    lo = (uint32_t)la | ((uint32_t)lb << 16);
}
__device__ __forceinline__ float ex2f(float x) {
    float y; asm("ex2.approx.f32 %0, %1;" : "=f"(y) : "f"(x)); return y;
}
__device__ __forceinline__ void ldmatrix_x4(uint32_t* r, uint32_t addr) {
    asm volatile("ldmatrix.sync.aligned.m8n8.x4.shared.b16 {%0,%1,%2,%3}, [%4];"
                 : "=r"(r[0]), "=r"(r[1]), "=r"(r[2]), "=r"(r[3]) : "r"(addr));
}
__device__ __forceinline__ void ldmatrix_x4t(uint32_t* r, uint32_t addr) {
    asm volatile("ldmatrix.sync.aligned.m8n8.x4.trans.shared.b16 {%0,%1,%2,%3}, [%4];"
                 : "=r"(r[0]), "=r"(r[1]), "=r"(r[2]), "=r"(r[3]) : "r"(addr));
}
__device__ __forceinline__ void mma_bf16(float* d, const uint32_t* a, const uint32_t* b) {
    asm volatile(
        "mma.sync.aligned.m16n8k16.row.col.f32.bf16.bf16.f32 "
        "{%0,%1,%2,%3}, {%4,%5,%6,%7}, {%8,%9}, {%0,%1,%2,%3};"
        : "+f"(d[0]), "+f"(d[1]), "+f"(d[2]), "+f"(d[3])
        : "r"(a[0]), "r"(a[1]), "r"(a[2]), "r"(a[3]), "r"(b[0]), "r"(b[1]));
}
__device__ __forceinline__ void cp_async16(uint32_t dst, const void* src) {
    asm volatile("cp.async.cg.shared.global [%0], [%1], 16;" :: "r"(dst), "l"(src));
}
__device__ __forceinline__ void cp_commit() {
    asm volatile("cp.async.commit_group;" ::: "memory");
}
__device__ __forceinline__ void cp_wait0() {
    asm volatile("cp.async.wait_group 0;" ::: "memory");
}

// ---------------- convert weights: W[k][n] fp32 -> transposed split bf16 ----------
__global__ void convert_w(const float* __restrict__ Wq, const float* __restrict__ Wk,
                          const float* __restrict__ Wv, const float* __restrict__ W1,
                          const float* __restrict__ W2)
{
    int id = blockIdx.x * 256 + threadIdx.x;      // < 131072
    const float* src; int K, n, k; size_t dofs;
    if (id < 98304) {
        int wi = id >> 15, rem = id & 32767;
        k = rem >> 7; n = rem & 127; K = 256;
        src = (wi == 0) ? Wq : (wi == 1) ? Wk : Wv;
        dofs = (size_t)wi * 32768;
    } else {
        int r2 = id - 98304;
        int wi = r2 >> 14, rem = r2 & 16383;
        k = rem >> 7; n = rem & 127; K = 128;
        src = wi ? W2 : W1;
        dofs = 98304 + (size_t)wi * 16384;
    }
    float x = src[(size_t)k * 128 + n];
    uint16_t h, l;
    split_bf16(x, h, l);
    size_t d = dofs + (size_t)n * K + k;
    ((uint16_t*)g_wh)[d] = h;
    ((uint16_t*)g_wl)[d] = l;
}

// ---------------- convert activations: concat(X,STE) -> split bf16 [M x 256] -----
__global__ void convert_a(const float* __restrict__ X, const float* __restrict__ STE)
{
    size_t id = (size_t)blockIdx.x * 256 + threadIdx.x;   // one per 8 elements
    int row = (int)(id >> 5);
    int c8  = (int)(id & 31) << 3;
    const float* src = (c8 < 128) ? (X + (size_t)row * 128 + c8)
                                  : (STE + (size_t)row * 128 + (c8 - 128));
    float4 v0 = ((const float4*)src)[0];
    float4 v1 = ((const float4*)src)[1];
    float vv[8] = {v0.x, v0.y, v0.z, v0.w, v1.x, v1.y, v1.z, v1.w};
    uint32_t hp[4], lp[4];
#pragma unroll
    for (int j = 0; j < 4; j++)
        split2(vv[2 * j], vv[2 * j + 1], hp[j], lp[j]);
    size_t e = (size_t)row * 256 + c8;
    *(uint4*)((uint16_t*)g_a_hi + e) = make_uint4(hp[0], hp[1], hp[2], hp[3]);
    *(uint4*)((uint16_t*)g_a_lo + e) = make_uint4(lp[0], lp[1], lp[2], lp[3]);
}

// ---------------- shared GEMM tile constants ------------------------------------
#define PADK 40                       // 80B row stride: 16B-aligned, ldmatrix conflict-free
#define MAT_BYTES (128 * PADK * 2)    // 10240
#define STAGE_BYTES (4 * MAT_BYTES)   // 40960
#define OFF_AH 0
#define OFF_AL MAT_BYTES
#define OFF_WH (2 * MAT_BYTES)
#define OFF_WL (3 * MAT_BYTES)
#define QKV_SMEM (2 * STAGE_BYTES)            // 81920
#define MLP_SMEM (2 * STAGE_BYTES + 20480)    // 102400

__device__ __forceinline__ void load_a_frags(uint32_t base_h, uint32_t base_l,
                                             int wm, int lane, int k0,
                                             uint32_t fah[4][4], uint32_t fal[4][4]) {
#pragma unroll
    for (int mi = 0; mi < 4; mi++) {
        uint32_t off = (uint32_t)((wm + mi * 16 + (lane & 15)) * PADK
                                  + k0 + ((lane >> 4) << 3)) * 2;
        ldmatrix_x4(fah[mi], base_h + off);
        ldmatrix_x4(fal[mi], base_l + off);
    }
}
__device__ __forceinline__ void load_b_frags(uint32_t base_h, uint32_t base_l,
                                             int wn, int lane, int k0,
                                             uint32_t fbh[4][2], uint32_t fbl[4][2]) {
#pragma unroll
    for (int njp = 0; njp < 2; njp++) {
        uint32_t off = (uint32_t)((wn + njp * 16 + ((lane >> 4) << 3) + (lane & 7)) * PADK
                                  + k0 + (((lane >> 3) & 1) << 3)) * 2;
        uint32_t t[4];
        ldmatrix_x4(t, base_h + off);
        fbh[2*njp][0] = t[0]; fbh[2*njp][1] = t[1];
        fbh[2*njp+1][0] = t[2]; fbh[2*njp+1][1] = t[3];
        ldmatrix_x4(t, base_l + off);
        fbl[2*njp][0] = t[0]; fbl[2*njp][1] = t[1];
        fbl[2*njp+1][0] = t[2]; fbl[2*njp+1][1] = t[3];
    }
}
__device__ __forceinline__ void mma_block(float acc[4][4][4],
                                          uint32_t fah[4][4], uint32_t fal[4][4],
                                          uint32_t fbh[4][2], uint32_t fbl[4][2]) {
#pragma unroll
    for (int mi = 0; mi < 4; mi++)
#pragma unroll
        for (int ni = 0; ni < 4; ni++) {
            mma_bf16(acc[mi][ni], fah[mi], fbh[ni]);
            mma_bf16(acc[mi][ni], fah[mi], fbl[ni]);
            mma_bf16(acc[mi][ni], fal[mi], fbh[ni]);
        }
}

// ---------------- fused QKV GEMM (unchanged from R9) -----------------------------
__global__ __launch_bounds__(256)
void qkv_gemm(const float* __restrict__ bq, const float* __restrict__ bk,
              const float* __restrict__ bv)
{
    extern __shared__ __align__(16) char smem[];
    const uint32_t sb = smem_u32(smem);

    const int wsel = blockIdx.x;
    const int row0 = blockIdx.y * 128;
    const __nv_bfloat16* __restrict__ Ah = g_a_hi;
    const __nv_bfloat16* __restrict__ Al = g_a_lo;
    const __nv_bfloat16* __restrict__ Wh = g_wh + wsel * 32768;
    const __nv_bfloat16* __restrict__ Wl = g_wl + wsel * 32768;
    const float* __restrict__ bias = (wsel == 0) ? bq : (wsel == 1) ? bk : bv;
    float* __restrict__ out = (wsel == 0) ? g_q : (wsel == 1) ? g_k : g_v;

    const int tid  = threadIdx.x;
    const int lane = tid & 31;
    const int wid  = tid >> 5;
    const int wm   = (wid & 1) * 64;
    const int wn   = (wid >> 1) * 32;

    float acc[4][4][4];
#pragma unroll
    for (int i = 0; i < 4; i++)
#pragma unroll
        for (int j = 0; j < 4; j++)
#pragma unroll
            for (int r = 0; r < 4; r++) acc[i][j][r] = 0.f;

    const int c0 = tid * 2;
    const int lr0 = c0 >> 2,        lc0 = (c0 & 3) << 3;
    const int lr1 = (c0 + 1) >> 2,  lc1 = ((c0 + 1) & 3) << 3;

    auto load_stage = [&](int kt, int buf) {
        uint32_t s = sb + buf * STAGE_BYTES;
        uint32_t d0 = (uint32_t)(lr0 * PADK + lc0) * 2;
        uint32_t d1 = (uint32_t)(lr1 * PADK + lc1) * 2;
        size_t gA0 = (size_t)(row0 + lr0) * 256 + kt + lc0;
        size_t gA1 = (size_t)(row0 + lr1) * 256 + kt + lc1;
        size_t gW0 = (size_t)lr0 * 256 + kt + lc0;
        size_t gW1 = (size_t)lr1 * 256 + kt + lc1;
        cp_async16(s + OFF_AH + d0, Ah + gA0);
        cp_async16(s + OFF_AH + d1, Ah + gA1);
        cp_async16(s + OFF_AL + d0, Al + gA0);
        cp_async16(s + OFF_AL + d1, Al + gA1);
        cp_async16(s + OFF_WH + d0, Wh + gW0);
        cp_async16(s + OFF_WH + d1, Wh + gW1);
        cp_async16(s + OFF_WL + d0, Wl + gW0);
        cp_async16(s + OFF_WL + d1, Wl + gW1);
    };

    const int NS = 8;
    load_stage(0, 0);
    cp_commit();

    for (int s = 0; s < NS; s++) {
        cp_wait0();
        __syncthreads();
        if (s + 1 < NS) { load_stage((s + 1) * 32, (s + 1) & 1); cp_commit(); }

        const uint32_t base = sb + (s & 1) * STAGE_BYTES;
#pragma unroll
        for (int ks = 0; ks < 2; ks++) {
            const int k0 = ks * 16;
            uint32_t fah[4][4], fal[4][4], fbh[4][2], fbl[4][2];
            load_a_frags(base + OFF_AH, base + OFF_AL, wm, lane, k0, fah, fal);
            load_b_frags(base + OFF_WH, base + OFF_WL, wn, lane, k0, fbh, fbl);
            mma_block(acc, fah, fal, fbh, fbl);
        }
    }

#pragma unroll
    for (int mi = 0; mi < 4; mi++) {
#pragma unroll
        for (int ni = 0; ni < 4; ni++) {
            int r0 = row0 + wm + mi * 16 + (lane >> 2);
            int c  = wn + ni * 8 + ((lane & 3) << 1);
            float b0 = bias[c], b1 = bias[c + 1];
            float v00 = fmaxf(acc[mi][ni][0] + b0, 0.f), v01 = fmaxf(acc[mi][ni][1] + b1, 0.f);
            float v10 = fmaxf(acc[mi][ni][2] + b0, 0.f), v11 = fmaxf(acc[mi][ni][3] + b1, 0.f);
            *(float2*)&out[(size_t)r0 * 128 + c]       = make_float2(v00, v01);
            *(float2*)&out[(size_t)(r0 + 8) * 128 + c] = make_float2(v10, v11);
        }
    }
}

// ---------------- fused MLP (unchanged from R9) ----------------------------------
__global__ __launch_bounds__(256)
void mlp_fused(const float* __restrict__ b1, const float* __restrict__ b2,
               float* __restrict__ out)
{
    extern __shared__ __align__(16) char smem[];
    const uint32_t sb = smem_u32(smem);

    const __nv_bfloat16* __restrict__ Ah = g_att_hi;
    const __nv_bfloat16* __restrict__ Al = g_att_lo;
    const __nv_bfloat16* __restrict__ W1h = g_wh + 98304;
    const __nv_bfloat16* __restrict__ W1l = g_wl + 98304;
    const __nv_bfloat16* __restrict__ W2h = g_wh + 114688;
    const __nv_bfloat16* __restrict__ W2l = g_wl + 114688;

    const int tid  = threadIdx.x;
    const int lane = tid & 31;
    const int wid  = tid >> 5;
    const int wm   = (wid & 1) * 64;
    const int wn   = (wid >> 1) * 32;
    const int row0 = blockIdx.x * 128;

    const int c0 = tid * 2;
    const int lr0 = c0 >> 2,        lc0 = (c0 & 3) << 3;
    const int lr1 = (c0 + 1) >> 2,  lc1 = ((c0 + 1) & 3) << 3;

    float acc[4][4][4];
#pragma unroll
    for (int i = 0; i < 4; i++)
#pragma unroll
        for (int j = 0; j < 4; j++)
#pragma unroll
            for (int r = 0; r < 4; r++) acc[i][j][r] = 0.f;

    auto load_stage1 = [&](int kt, int buf) {
        uint32_t s = sb + buf * STAGE_BYTES;
        uint32_t d0 = (uint32_t)(lr0 * PADK + lc0) * 2;
        uint32_t d1 = (uint32_t)(lr1 * PADK + lc1) * 2;
        size_t gA0 = (size_t)(row0 + lr0) * 128 + kt + lc0;
        size_t gA1 = (size_t)(row0 + lr1) * 128 + kt + lc1;
        size_t gW0 = (size_t)lr0 * 128 + kt + lc0;
        size_t gW1 = (size_t)lr1 * 128 + kt + lc1;
        cp_async16(s + OFF_AH + d0, Ah + gA0);
        cp_async16(s + OFF_AH + d1, Ah + gA1);
        cp_async16(s + OFF_AL + d0, Al + gA0);
        cp_async16(s + OFF_AL + d1, Al + gA1);
        cp_async16(s + OFF_WH + d0, W1h + gW0);
        cp_async16(s + OFF_WH + d1, W1h + gW1);
        cp_async16(s + OFF_WL + d0, W1l + gW0);
        cp_async16(s + OFF_WL + d1, W1l + gW1);
    };

    load_stage1(0, 0);
    cp_commit();
    for (int s = 0; s < 4; s++) {
        cp_wait0();
        __syncthreads();
        if (s + 1 < 4) { load_stage1((s + 1) * 32, (s + 1) & 1); cp_commit(); }
        const uint32_t base = sb + (s & 1) * STAGE_BYTES;
#pragma unroll
        for (int ks = 0; ks < 2; ks++) {
            const int k0 = ks * 16;
            uint32_t fah[4][4], fal[4][4], fbh[4][2], fbl[4][2];
            load_a_frags(base + OFF_AH, base + OFF_AL, wm, lane, k0, fah, fal);
            load_b_frags(base + OFF_WH, base + OFF_WL, wn, lane, k0, fbh, fbl);
            mma_block(acc, fah, fal, fbh, fbl);
        }
    }
    __syncthreads();

#pragma unroll
    for (int mi = 0; mi < 4; mi++) {
#pragma unroll
        for (int ni = 0; ni < 4; ni++) {
            int r  = wm + mi * 16 + (lane >> 2);
            int c  = wn + ni * 8 + ((lane & 3) << 1);
            int kc = c >> 5, cc = c & 31;
            uint32_t hbase = sb + (uint32_t)kc * (2 * MAT_BYTES);
            float b0 = b1[c], bb1 = b1[c + 1];
            float v00 = fmaxf(acc[mi][ni][0] + b0, 0.f), v01 = fmaxf(acc[mi][ni][1] + bb1, 0.f);
            float v10 = fmaxf(acc[mi][ni][2] + b0, 0.f), v11 = fmaxf(acc[mi][ni][3] + bb1, 0.f);
            uint32_t hi, lo;
            split2(v00, v01, hi, lo);
            asm volatile("st.shared.b32 [%0], %1;" :: "r"(hbase + (uint32_t)(r * PADK + cc) * 2), "r"(hi) : "memory");
            asm volatile("st.shared.b32 [%0], %1;" :: "r"(hbase + MAT_BYTES + (uint32_t)(r * PADK + cc) * 2), "r"(lo) : "memory");
            split2(v10, v11, hi, lo);
            asm volatile("st.shared.b32 [%0], %1;" :: "r"(hbase + (uint32_t)((r + 8) * PADK + cc) * 2), "r"(hi) : "memory");
            asm volatile("st.shared.b32 [%0], %1;" :: "r"(hbase + MAT_BYTES + (uint32_t)((r + 8) * PADK + cc) * 2), "r"(lo) : "memory");
        }
    }

#pragma unroll
    for (int i = 0; i < 4; i++)
#pragma unroll
        for (int j = 0; j < 4; j++)
#pragma unroll
            for (int r = 0; r < 4; r++) acc[i][j][r] = 0.f;

    const uint32_t w2base = sb + 2 * STAGE_BYTES;
    for (int kc = 0; kc < 4; kc++) {
        {
            uint32_t d0 = (uint32_t)(lr0 * PADK + lc0) * 2;
            uint32_t d1 = (uint32_t)(lr1 * PADK + lc1) * 2;
            size_t gW0 = (size_t)lr0 * 128 + kc * 32 + lc0;
            size_t gW1 = (size_t)lr1 * 128 + kc * 32 + lc1;
            cp_async16(w2base + d0,             W2h + gW0);
            cp_async16(w2base + d1,             W2h + gW1);
            cp_async16(w2base + MAT_BYTES + d0, W2l + gW0);
            cp_async16(w2base + MAT_BYTES + d1, W2l + gW1);
        }
        cp_commit();
        cp_wait0();
        __syncthreads();

        const uint32_t hbase = sb + (uint32_t)kc * (2 * MAT_BYTES);
#pragma unroll
        for (int ks = 0; ks < 2; ks++) {
            const int k0 = ks * 16;
            uint32_t fah[4][4], fal[4][4], fbh[4][2], fbl[4][2];
            load_a_frags(hbase, hbase + MAT_BYTES, wm, lane, k0, fah, fal);
            load_b_frags(w2base, w2base + MAT_BYTES, wn, lane, k0, fbh, fbl);
            mma_block(acc, fah, fal, fbh, fbl);
        }
        __syncthreads();
    }

#pragma unroll
    for (int mi = 0; mi < 4; mi++) {
#pragma unroll
        for (int ni = 0; ni < 4; ni++) {
            int r0 = row0 + wm + mi * 16 + (lane >> 2);
            int c  = wn + ni * 8 + ((lane & 3) << 1);
            float b0 = b2[c], bb1 = b2[c + 1];
            *(float2*)&out[(size_t)r0 * 128 + c] =
                make_float2(acc[mi][ni][0] + b0, acc[mi][ni][1] + bb1);
            *(float2*)&out[(size_t)(r0 + 8) * 128 + c] =
                make_float2(acc[mi][ni][2] + b0, acc[mi][ni][3] + bb1);
        }
    }
}

// ---------------- MMA flash-attention -------------------------------------------
// Block per (n, b): 256 threads = 8 warps, warp w == head w. Q/K/V for all heads
// staged split-bf16 in smem [p][136] (272B rows, conflict-free ldmatrix; head h
// 16B-aligned at col h*16). Per 16-query m-tile: S = Q@K^T (3-term split MMA,
// causal tiles skipped), softmax in acc regs, P@V (P packed from acc into
// A-frags, V via ldmatrix.trans, 3-term split). Output split-bf16 to g_att.
#define ATT_PAD 136
#define ATT_MAT (128 * ATT_PAD * 2)    // 34816
#define ATT_SMEM (6 * ATT_MAT)         // 208896

__global__ __launch_bounds__(256)
void attn_mma()
{
    extern __shared__ __align__(16) char smem[];
    const uint32_t sb = smem_u32(smem);

    const int n = blockIdx.x;
    const int b = blockIdx.y;
    const int tid = threadIdx.x, lane = tid & 31, h = tid >> 5;

    const size_t rowbase = (size_t)(b * 128) * 256 + n;    // global row of p=0

    // ---- stage Q,K,V: fp32 -> split bf16 into smem ----
    {
        const float* srcs[3] = { g_q, g_k, g_v };
#pragma unroll
        for (int tsel = 0; tsel < 3; tsel++) {
            const float* __restrict__ src = srcs[tsel];
            uint32_t dh = sb + (uint32_t)(2 * tsel) * ATT_MAT;
            uint32_t dl = dh + ATT_MAT;
#pragma unroll
            for (int i = 0; i < 16; i++) {
                int id = tid + i * 256;          // 0..4095
                int p  = id >> 5;
                int c4 = (id & 31) * 4;
                float4 f = *(const float4*)(src + (rowbase + (size_t)p * 256) * 128 + c4);
                uint32_t hi0, lo0, hi1, lo1;
                split2(f.x, f.y, hi0, lo0);
                split2(f.z, f.w, hi1, lo1);
                uint32_t off = (uint32_t)(p * ATT_PAD + c4) * 2;
                asm volatile("st.shared.v2.b32 [%0], {%1,%2};" :: "r"(dh + off), "r"(hi0), "r"(hi1) : "memory");
                asm volatile("st.shared.v2.b32 [%0], {%1,%2};" :: "r"(dl + off), "r"(lo0), "r"(lo1) : "memory");
            }
        }
    }
    __syncthreads();

    const uint32_t sqh = sb,                sql = sb + ATT_MAT;
    const uint32_t skh = sb + 2 * ATT_MAT,  skl = sb + 3 * ATT_MAT;
    const uint32_t svh = sb + 4 * ATT_MAT,  svl = sb + 5 * ATT_MAT;
    const uint32_t hoff = (uint32_t)h * 32;          // head byte offset in row

    const int g  = lane >> 2;        // row within 8-row group
    const int tq = lane & 3;         // col pair index
    const float C = 0.36067376022224085f;    // log2(e) / sqrt(16)

#pragma unroll 1
    for (int mt = 0; mt < 8; mt++) {
        // Q fragments for rows mt*16..mt*16+15
        uint32_t qh[4], ql[4];
        {
            uint32_t off = (uint32_t)((mt * 16 + (lane & 15)) * ATT_PAD) * 2
                           + hoff + (uint32_t)((lane >> 4) << 4);
            ldmatrix_x4(qh, sqh + off);
            ldmatrix_x4(ql, sql + off);
        }

        float S[16][4];
        const int ntiles = 2 * mt + 2;
        for (int j = 0; j < ntiles; j++)
#pragma unroll
            for (int e = 0; e < 4; e++) S[j][e] = 0.f;

        // S = Q @ K^T over needed key tiles
        for (int jp = 0; jp <= mt; jp++) {
            uint32_t kh0[2], kh1[2], kl0[2], kl1[2];
            {
                uint32_t off = (uint32_t)((jp * 16 + ((lane >> 4) << 3) + (lane & 7)) * ATT_PAD) * 2
                               + hoff + (uint32_t)(((lane >> 3) & 1) << 4);
                uint32_t t[4];
                ldmatrix_x4(t, skh + off);
                kh0[0] = t[0]; kh0[1] = t[1]; kh1[0] = t[2]; kh1[1] = t[3];
                ldmatrix_x4(t, skl + off);
                kl0[0] = t[0]; kl0[1] = t[1]; kl1[0] = t[2]; kl1[1] = t[3];
            }
            mma_bf16(S[2*jp],   qh, kh0); mma_bf16(S[2*jp],   qh, kl0); mma_bf16(S[2*jp],   ql, kh0);
            mma_bf16(S[2*jp+1], qh, kh1); mma_bf16(S[2*jp+1], qh, kl1); mma_bf16(S[2*jp+1], ql, kh1);
        }

        // causal mask + row max
        const int p0 = mt * 16 + g, p1 = p0 + 8;
        float mx0 = -1e30f, mx1 = -1e30f;
        for (int j = 0; j < ntiles; j++) {
            int key0 = j * 8 + tq * 2, key1 = key0 + 1;
            if (key0 > p0) S[j][0] = -1e30f;
            if (key1 > p0) S[j][1] = -1e30f;
            if (key0 > p1) S[j][2] = -1e30f;
            if (key1 > p1) S[j][3] = -1e30f;
            mx0 = fmaxf(mx0, fmaxf(S[j][0], S[j][1]));
            mx1 = fmaxf(mx1, fmaxf(S[j][2], S[j][3]));
        }
        mx0 = fmaxf(mx0, __shfl_xor_sync(0xffffffffu, mx0, 1));
        mx0 = fmaxf(mx0, __shfl_xor_sync(0xffffffffu, mx0, 2));
        mx1 = fmaxf(mx1, __shfl_xor_sync(0xffffffffu, mx1, 1));
        mx1 = fmaxf(mx1, __shfl_xor_sync(0xffffffffu, mx1, 2));

        // exp + row sum (weights left unnormalized; normalize after PV)
        float sum0 = 0.f, sum1 = 0.f;
        for (int j = 0; j < ntiles; j++) {
            S[j][0] = ex2f((S[j][0] - mx0) * C);
            S[j][1] = ex2f((S[j][1] - mx0) * C);
            S[j][2] = ex2f((S[j][2] - mx1) * C);
            S[j][3] = ex2f((S[j][3] - mx1) * C);
            sum0 += S[j][0] + S[j][1];
            sum1 += S[j][2] + S[j][3];
        }
        sum0 += __shfl_xor_sync(0xffffffffu, sum0, 1);
        sum0 += __shfl_xor_sync(0xffffffffu, sum0, 2);
        sum1 += __shfl_xor_sync(0xffffffffu, sum1, 1);
        sum1 += __shfl_xor_sync(0xffffffffu, sum1, 2);

        // PV: attended[16 x 16] = P @ V
        float o0[4] = {0.f, 0.f, 0.f, 0.f};
        float o1[4] = {0.f, 0.f, 0.f, 0.f};
        for (int c = 0; c <= mt; c++) {
            uint32_t vh0[2], vh1[2], vl0[2], vl1[2];
            {
                uint32_t off = (uint32_t)((c * 16 + (((lane >> 3) & 1) << 3) + (lane & 7)) * ATT_PAD) * 2
                               + hoff + (uint32_t)((lane >> 4) << 4);
                uint32_t t[4];
                ldmatrix_x4t(t, svh + off);
                vh0[0] = t[0]; vh0[1] = t[1]; vh1[0] = t[2]; vh1[1] = t[3];
                ldmatrix_x4t(t, svl + off);
                vl0[0] = t[0]; vl0[1] = t[1]; vl1[0] = t[2]; vl1[1] = t[3];
            }
            // P A-frags straight from S accumulators (split)
            uint32_t ph[4], pl[4];
            split2(S[2*c][0],   S[2*c][1],   ph[0], pl[0]);
            split2(S[2*c][2],   S[2*c][3],   ph[1], pl[1]);
            split2(S[2*c+1][0], S[2*c+1][1], ph[2], pl[2]);
            split2(S[2*c+1][2], S[2*c+1][3], ph[3], pl[3]);

            mma_bf16(o0, ph, vh0); mma_bf16(o0, ph, vl0); mma_bf16(o0, pl, vh0);
            mma_bf16(o1, ph, vh1); mma_bf16(o1, ph, vl1); mma_bf16(o1, pl, vh1);
        }

        // normalize + write split bf16 to g_att
        const float inv0 = 1.f / sum0, inv1 = 1.f / sum1;
        const size_t r0b = (rowbase + (size_t)p0 * 256) * 128 + h * 16 + tq * 2;
        const size_t r1b = (rowbase + (size_t)p1 * 256) * 128 + h * 16 + tq * 2;
        uint32_t hi, lo;
        split2(o0[0] * inv0, o0[1] * inv0, hi, lo);
        *(uint32_t*)((uint16_t*)g_att_hi + r0b) = hi;
        *(uint32_t*)((uint16_t*)g_att_lo + r0b) = lo;
        split2(o0[2] * inv1, o0[3] * inv1, hi, lo);
        *(uint32_t*)((uint16_t*)g_att_hi + r1b) = hi;
        *(uint32_t*)((uint16_t*)g_att_lo + r1b) = lo;
        split2(o1[0] * inv0, o1[1] * inv0, hi, lo);
        *(uint32_t*)((uint16_t*)g_att_hi + r0b + 8) = hi;
        *(uint32_t*)((uint16_t*)g_att_lo + r0b + 8) = lo;
        split2(o1[2] * inv1, o1[3] * inv1, hi, lo);
        *(uint32_t*)((uint16_t*)g_att_hi + r1b + 8) = hi;
        *(uint32_t*)((uint16_t*)g_att_lo + r1b + 8) = lo;
    }
}

// ---------------- launch -------------------------------------------------------
extern "C" void kernel_launch(void* const* d_in, const int* in_sizes, int n_in,
                              void* d_out, int out_size)
{
    const float* X   = (const float*)d_in[0];
    const float* STE = (const float*)d_in[1];
    const float* Wq  = (const float*)d_in[2];
    const float* bq  = (const float*)d_in[3];
    const float* Wk  = (const float*)d_in[4];
    const float* bk  = (const float*)d_in[5];
    const float* Wv  = (const float*)d_in[6];
    const float* bv  = (const float*)d_in[7];
    const float* W1  = (const float*)d_in[8];
    const float* b1  = (const float*)d_in[9];
    const float* W2  = (const float*)d_in[10];
    const float* b2  = (const float*)d_in[11];
    float* out = (float*)d_out;

    cudaFuncSetAttribute(qkv_gemm,  cudaFuncAttributeMaxDynamicSharedMemorySize, QKV_SMEM);
    cudaFuncSetAttribute(mlp_fused, cudaFuncAttributeMaxDynamicSharedMemorySize, MLP_SMEM);
    cudaFuncSetAttribute(attn_mma,  cudaFuncAttributeMaxDynamicSharedMemorySize, ATT_SMEM);

    // preprocessing: weight transpose+split, activation concat+split
    convert_w<<<512, 256>>>(Wq, Wk, Wv, W1, W2);
    convert_a<<<32768, 256>>>(X, STE);

    // fused QKV projections (x = weight select -> L2-shared A tiles)
    qkv_gemm<<<dim3(3, M_ / 128), 256, QKV_SMEM>>>(bq, bk, bv);

    // MMA flash-attention: block per (n, b), warp per head
    attn_mma<<<dim3(N_, B_), 256, ATT_SMEM>>>();

    // fused output MLP
    mlp_fused<<<M_ / 128, 256, MLP_SMEM>>>(b1, b2, out);
}

// round 11
// speedup vs baseline: 1.0311x; 1.0311x over previous
#include <cuda_runtime.h>
#include <cuda_bf16.h>
#include <math.h>
#include <stdint.h>

#define B_   8
#define P_   128
#define N_   256
#define D_   128
#define M_   (B_*P_*N_)        // 262144 rows

// ---------------- scratch (device globals; no allocation allowed) ----------------
__device__ __align__(16) __nv_bfloat16 g_a_hi[(size_t)M_ * 256];
__device__ __align__(16) __nv_bfloat16 g_a_lo[(size_t)M_ * 256];
__device__ __align__(16) __nv_bfloat16 g_q_hi[(size_t)M_ * D_];
__device__ __align__(16) __nv_bfloat16 g_q_lo[(size_t)M_ * D_];
__device__ __align__(16) __nv_bfloat16 g_k_hi[(size_t)M_ * D_];
__device__ __align__(16) __nv_bfloat16 g_k_lo[(size_t)M_ * D_];
__device__ __align__(16) __nv_bfloat16 g_v_hi[(size_t)M_ * D_];
__device__ __align__(16) __nv_bfloat16 g_v_lo[(size_t)M_ * D_];
__device__ __align__(16) __nv_bfloat16 g_att_hi[(size_t)M_ * D_];
__device__ __align__(16) __nv_bfloat16 g_att_lo[(size_t)M_ * D_];
// weights transposed to [n][k], bf16-split. layout: Wq(32768) Wk Wv W1(16384) W2
__device__ __align__(16) __nv_bfloat16 g_wh[131072];
__device__ __align__(16) __nv_bfloat16 g_wl[131072];

// ---------------- helpers ----------------
__device__ __forceinline__ uint32_t smem_u32(const void* p) {
    uint32_t a;
    asm("{ .reg .u64 t; cvta.to.shared.u64 t, %1; cvt.u32.u64 %0, t; }" : "=r"(a) : "l"(p));
    return a;
}
__device__ __forceinline__ void split_bf16(float x, uint16_t& h, uint16_t& l) {
    __nv_bfloat16 hb = __float2bfloat16(x);
    __nv_bfloat16 lb = __float2bfloat16(x - __bfloat162float(hb));
    h = __bfloat16_as_ushort(hb);
    l = __bfloat16_as_ushort(lb);
}
__device__ __forceinline__ void split2(float a, float b, uint32_t& hi, uint32_t& lo) {
    uint16_t ha, la, hb, lb;
    split_bf16(a, ha, la);
    split_bf16(b, hb, lb);
    hi = (uint32_t)ha | ((uint32_t)hb << 16);
    lo = (uint32_t)la | ((uint32_t)lb << 16);
}
__device__ __forceinline__ float ex2f(float x) {
    float y; asm("ex2.approx.f32 %0, %1;" : "=f"(y) : "f"(x)); return y;
}
__device__ __forceinline__ void ldmatrix_x4(uint32_t* r, uint32_t addr) {
    asm volatile("ldmatrix.sync.aligned.m8n8.x4.shared.b16 {%0,%1,%2,%3}, [%4];"
                 : "=r"(r[0]), "=r"(r[1]), "=r"(r[2]), "=r"(r[3]) : "r"(addr));
}
__device__ __forceinline__ void ldmatrix_x4t(uint32_t* r, uint32_t addr) {
    asm volatile("ldmatrix.sync.aligned.m8n8.x4.trans.shared.b16 {%0,%1,%2,%3}, [%4];"
                 : "=r"(r[0]), "=r"(r[1]), "=r"(r[2]), "=r"(r[3]) : "r"(addr));
}
__device__ __forceinline__ void mma_bf16(float* d, const uint32_t* a, const uint32_t* b) {
    asm volatile(
        "mma.sync.aligned.m16n8k16.row.col.f32.bf16.bf16.f32 "
        "{%0,%1,%2,%3}, {%4,%5,%6,%7}, {%8,%9}, {%0,%1,%2,%3};"
        : "+f"(d[0]), "+f"(d[1]), "+f"(d[2]), "+f"(d[3])
        : "r"(a[0]), "r"(a[1]), "r"(a[2]), "r"(a[3]), "r"(b[0]), "r"(b[1]));
}
__device__ __forceinline__ void cp_async16(uint32_t dst, const void* src) {
    asm volatile("cp.async.cg.shared.global [%0], [%1], 16;" :: "r"(dst), "l"(src));
}
__device__ __forceinline__ void cp_commit() {
    asm volatile("cp.async.commit_group;" ::: "memory");
}
__device__ __forceinline__ void cp_wait0() {
    asm volatile("cp.async.wait_group 0;" ::: "memory");
}

// ---------------- convert weights: W[k][n] fp32 -> transposed split bf16 ----------
__global__ void convert_w(const float* __restrict__ Wq, const float* __restrict__ Wk,
                          const float* __restrict__ Wv, const float* __restrict__ W1,
                          const float* __restrict__ W2)
{
    int id = blockIdx.x * 256 + threadIdx.x;      // < 131072
    const float* src; int K, n, k; size_t dofs;
    if (id < 98304) {
        int wi = id >> 15, rem = id & 32767;
        k = rem >> 7; n = rem & 127; K = 256;
        src = (wi == 0) ? Wq : (wi == 1) ? Wk : Wv;
        dofs = (size_t)wi * 32768;
    } else {
        int r2 = id - 98304;
        int wi = r2 >> 14, rem = r2 & 16383;
        k = rem >> 7; n = rem & 127; K = 128;
        src = wi ? W2 : W1;
        dofs = 98304 + (size_t)wi * 16384;
    }
    float x = src[(size_t)k * 128 + n];
    uint16_t h, l;
    split_bf16(x, h, l);
    size_t d = dofs + (size_t)n * K + k;
    ((uint16_t*)g_wh)[d] = h;
    ((uint16_t*)g_wl)[d] = l;
}

// ---------------- convert activations: concat(X,STE) -> split bf16 [M x 256] -----
__global__ void convert_a(const float* __restrict__ X, const float* __restrict__ STE)
{
    size_t id = (size_t)blockIdx.x * 256 + threadIdx.x;   // one per 8 elements
    int row = (int)(id >> 5);
    int c8  = (int)(id & 31) << 3;
    const float* src = (c8 < 128) ? (X + (size_t)row * 128 + c8)
                                  : (STE + (size_t)row * 128 + (c8 - 128));
    float4 v0 = ((const float4*)src)[0];
    float4 v1 = ((const float4*)src)[1];
    float vv[8] = {v0.x, v0.y, v0.z, v0.w, v1.x, v1.y, v1.z, v1.w};
    uint32_t hp[4], lp[4];
#pragma unroll
    for (int j = 0; j < 4; j++)
        split2(vv[2 * j], vv[2 * j + 1], hp[j], lp[j]);
    size_t e = (size_t)row * 256 + c8;
    *(uint4*)((uint16_t*)g_a_hi + e) = make_uint4(hp[0], hp[1], hp[2], hp[3]);
    *(uint4*)((uint16_t*)g_a_lo + e) = make_uint4(lp[0], lp[1], lp[2], lp[3]);
}

// ---------------- shared GEMM tile constants ------------------------------------
#define PADK 40                       // 80B row stride: 16B-aligned, ldmatrix conflict-free
#define MAT_BYTES (128 * PADK * 2)    // 10240
#define STAGE_BYTES (4 * MAT_BYTES)   // 40960
#define OFF_AH 0
#define OFF_AL MAT_BYTES
#define OFF_WH (2 * MAT_BYTES)
#define OFF_WL (3 * MAT_BYTES)
#define QKV_SMEM (2 * STAGE_BYTES)            // 81920
#define MLP_SMEM (2 * STAGE_BYTES + 20480)    // 102400

__device__ __forceinline__ void load_a_frags(uint32_t base_h, uint32_t base_l,
                                             int wm, int lane, int k0,
                                             uint32_t fah[4][4], uint32_t fal[4][4]) {
#pragma unroll
    for (int mi = 0; mi < 4; mi++) {
        uint32_t off = (uint32_t)((wm + mi * 16 + (lane & 15)) * PADK
                                  + k0 + ((lane >> 4) << 3)) * 2;
        ldmatrix_x4(fah[mi], base_h + off);
        ldmatrix_x4(fal[mi], base_l + off);
    }
}
__device__ __forceinline__ void load_b_frags(uint32_t base_h, uint32_t base_l,
                                             int wn, int lane, int k0,
                                             uint32_t fbh[4][2], uint32_t fbl[4][2]) {
#pragma unroll
    for (int njp = 0; njp < 2; njp++) {
        uint32_t off = (uint32_t)((wn + njp * 16 + ((lane >> 4) << 3) + (lane & 7)) * PADK
                                  + k0 + (((lane >> 3) & 1) << 3)) * 2;
        uint32_t t[4];
        ldmatrix_x4(t, base_h + off);
        fbh[2*njp][0] = t[0]; fbh[2*njp][1] = t[1];
        fbh[2*njp+1][0] = t[2]; fbh[2*njp+1][1] = t[3];
        ldmatrix_x4(t, base_l + off);
        fbl[2*njp][0] = t[0]; fbl[2*njp][1] = t[1];
        fbl[2*njp+1][0] = t[2]; fbl[2*njp+1][1] = t[3];
    }
}
__device__ __forceinline__ void mma_block(float acc[4][4][4],
                                          uint32_t fah[4][4], uint32_t fal[4][4],
                                          uint32_t fbh[4][2], uint32_t fbl[4][2]) {
#pragma unroll
    for (int mi = 0; mi < 4; mi++)
#pragma unroll
        for (int ni = 0; ni < 4; ni++) {
            mma_bf16(acc[mi][ni], fah[mi], fbh[ni]);
            mma_bf16(acc[mi][ni], fah[mi], fbl[ni]);
            mma_bf16(acc[mi][ni], fal[mi], fbh[ni]);
        }
}

// ---------------- fused QKV GEMM (epilogue now writes split bf16) -----------------
__global__ __launch_bounds__(256)
void qkv_gemm(const float* __restrict__ bq, const float* __restrict__ bk,
              const float* __restrict__ bv)
{
    extern __shared__ __align__(16) char smem[];
    const uint32_t sb = smem_u32(smem);

    const int wsel = blockIdx.x;
    const int row0 = blockIdx.y * 128;
    const __nv_bfloat16* __restrict__ Ah = g_a_hi;
    const __nv_bfloat16* __restrict__ Al = g_a_lo;
    const __nv_bfloat16* __restrict__ Wh = g_wh + wsel * 32768;
    const __nv_bfloat16* __restrict__ Wl = g_wl + wsel * 32768;
    const float* __restrict__ bias = (wsel == 0) ? bq : (wsel == 1) ? bk : bv;
    uint16_t* __restrict__ oh = (uint16_t*)((wsel == 0) ? g_q_hi : (wsel == 1) ? g_k_hi : g_v_hi);
    uint16_t* __restrict__ ol = (uint16_t*)((wsel == 0) ? g_q_lo : (wsel == 1) ? g_k_lo : g_v_lo);

    const int tid  = threadIdx.x;
    const int lane = tid & 31;
    const int wid  = tid >> 5;
    const int wm   = (wid & 1) * 64;
    const int wn   = (wid >> 1) * 32;

    float acc[4][4][4];
#pragma unroll
    for (int i = 0; i < 4; i++)
#pragma unroll
        for (int j = 0; j < 4; j++)
#pragma unroll
            for (int r = 0; r < 4; r++) acc[i][j][r] = 0.f;

    const int c0 = tid * 2;
    const int lr0 = c0 >> 2,        lc0 = (c0 & 3) << 3;
    const int lr1 = (c0 + 1) >> 2,  lc1 = ((c0 + 1) & 3) << 3;

    auto load_stage = [&](int kt, int buf) {
        uint32_t s = sb + buf * STAGE_BYTES;
        uint32_t d0 = (uint32_t)(lr0 * PADK + lc0) * 2;
        uint32_t d1 = (uint32_t)(lr1 * PADK + lc1) * 2;
        size_t gA0 = (size_t)(row0 + lr0) * 256 + kt + lc0;
        size_t gA1 = (size_t)(row0 + lr1) * 256 + kt + lc1;
        size_t gW0 = (size_t)lr0 * 256 + kt + lc0;
        size_t gW1 = (size_t)lr1 * 256 + kt + lc1;
        cp_async16(s + OFF_AH + d0, Ah + gA0);
        cp_async16(s + OFF_AH + d1, Ah + gA1);
        cp_async16(s + OFF_AL + d0, Al + gA0);
        cp_async16(s + OFF_AL + d1, Al + gA1);
        cp_async16(s + OFF_WH + d0, Wh + gW0);
        cp_async16(s + OFF_WH + d1, Wh + gW1);
        cp_async16(s + OFF_WL + d0, Wl + gW0);
        cp_async16(s + OFF_WL + d1, Wl + gW1);
    };

    const int NS = 8;
    load_stage(0, 0);
    cp_commit();

    for (int s = 0; s < NS; s++) {
        cp_wait0();
        __syncthreads();
        if (s + 1 < NS) { load_stage((s + 1) * 32, (s + 1) & 1); cp_commit(); }

        const uint32_t base = sb + (s & 1) * STAGE_BYTES;
#pragma unroll
        for (int ks = 0; ks < 2; ks++) {
            const int k0 = ks * 16;
            uint32_t fah[4][4], fal[4][4], fbh[4][2], fbl[4][2];
            load_a_frags(base + OFF_AH, base + OFF_AL, wm, lane, k0, fah, fal);
            load_b_frags(base + OFF_WH, base + OFF_WL, wn, lane, k0, fbh, fbl);
            mma_block(acc, fah, fal, fbh, fbl);
        }
    }

#pragma unroll
    for (int mi = 0; mi < 4; mi++) {
#pragma unroll
        for (int ni = 0; ni < 4; ni++) {
            int r0 = row0 + wm + mi * 16 + (lane >> 2);
            int c  = wn + ni * 8 + ((lane & 3) << 1);
            float b0 = bias[c], b1 = bias[c + 1];
            float v00 = fmaxf(acc[mi][ni][0] + b0, 0.f), v01 = fmaxf(acc[mi][ni][1] + b1, 0.f);
            float v10 = fmaxf(acc[mi][ni][2] + b0, 0.f), v11 = fmaxf(acc[mi][ni][3] + b1, 0.f);
            uint32_t hi, lo;
            split2(v00, v01, hi, lo);
            *(uint32_t*)(oh + (size_t)r0 * 128 + c) = hi;
            *(uint32_t*)(ol + (size_t)r0 * 128 + c) = lo;
            split2(v10, v11, hi, lo);
            *(uint32_t*)(oh + (size_t)(r0 + 8) * 128 + c) = hi;
            *(uint32_t*)(ol + (size_t)(r0 + 8) * 128 + c) = lo;
        }
    }
}

// ---------------- fused MLP (unchanged from R9) ----------------------------------
__global__ __launch_bounds__(256)
void mlp_fused(const float* __restrict__ b1, const float* __restrict__ b2,
               float* __restrict__ out)
{
    extern __shared__ __align__(16) char smem[];
    const uint32_t sb = smem_u32(smem);

    const __nv_bfloat16* __restrict__ Ah = g_att_hi;
    const __nv_bfloat16* __restrict__ Al = g_att_lo;
    const __nv_bfloat16* __restrict__ W1h = g_wh + 98304;
    const __nv_bfloat16* __restrict__ W1l = g_wl + 98304;
    const __nv_bfloat16* __restrict__ W2h = g_wh + 114688;
    const __nv_bfloat16* __restrict__ W2l = g_wl + 114688;

    const int tid  = threadIdx.x;
    const int lane = tid & 31;
    const int wid  = tid >> 5;
    const int wm   = (wid & 1) * 64;
    const int wn   = (wid >> 1) * 32;
    const int row0 = blockIdx.x * 128;

    const int c0 = tid * 2;
    const int lr0 = c0 >> 2,        lc0 = (c0 & 3) << 3;
    const int lr1 = (c0 + 1) >> 2,  lc1 = ((c0 + 1) & 3) << 3;

    float acc[4][4][4];
#pragma unroll
    for (int i = 0; i < 4; i++)
#pragma unroll
        for (int j = 0; j < 4; j++)
#pragma unroll
            for (int r = 0; r < 4; r++) acc[i][j][r] = 0.f;

    auto load_stage1 = [&](int kt, int buf) {
        uint32_t s = sb + buf * STAGE_BYTES;
        uint32_t d0 = (uint32_t)(lr0 * PADK + lc0) * 2;
        uint32_t d1 = (uint32_t)(lr1 * PADK + lc1) * 2;
        size_t gA0 = (size_t)(row0 + lr0) * 128 + kt + lc0;
        size_t gA1 = (size_t)(row0 + lr1) * 128 + kt + lc1;
        size_t gW0 = (size_t)lr0 * 128 + kt + lc0;
        size_t gW1 = (size_t)lr1 * 128 + kt + lc1;
        cp_async16(s + OFF_AH + d0, Ah + gA0);
        cp_async16(s + OFF_AH + d1, Ah + gA1);
        cp_async16(s + OFF_AL + d0, Al + gA0);
        cp_async16(s + OFF_AL + d1, Al + gA1);
        cp_async16(s + OFF_WH + d0, W1h + gW0);
        cp_async16(s + OFF_WH + d1, W1h + gW1);
        cp_async16(s + OFF_WL + d0, W1l + gW0);
        cp_async16(s + OFF_WL + d1, W1l + gW1);
    };

    load_stage1(0, 0);
    cp_commit();
    for (int s = 0; s < 4; s++) {
        cp_wait0();
        __syncthreads();
        if (s + 1 < 4) { load_stage1((s + 1) * 32, (s + 1) & 1); cp_commit(); }
        const uint32_t base = sb + (s & 1) * STAGE_BYTES;
#pragma unroll
        for (int ks = 0; ks < 2; ks++) {
            const int k0 = ks * 16;
            uint32_t fah[4][4], fal[4][4], fbh[4][2], fbl[4][2];
            load_a_frags(base + OFF_AH, base + OFF_AL, wm, lane, k0, fah, fal);
            load_b_frags(base + OFF_WH, base + OFF_WL, wn, lane, k0, fbh, fbl);
            mma_block(acc, fah, fal, fbh, fbl);
        }
    }
    __syncthreads();

#pragma unroll
    for (int mi = 0; mi < 4; mi++) {
#pragma unroll
        for (int ni = 0; ni < 4; ni++) {
            int r  = wm + mi * 16 + (lane >> 2);
            int c  = wn + ni * 8 + ((lane & 3) << 1);
            int kc = c >> 5, cc = c & 31;
            uint32_t hbase = sb + (uint32_t)kc * (2 * MAT_BYTES);
            float b0 = b1[c], bb1 = b1[c + 1];
            float v00 = fmaxf(acc[mi][ni][0] + b0, 0.f), v01 = fmaxf(acc[mi][ni][1] + bb1, 0.f);
            float v10 = fmaxf(acc[mi][ni][2] + b0, 0.f), v11 = fmaxf(acc[mi][ni][3] + bb1, 0.f);
            uint32_t hi, lo;
            split2(v00, v01, hi, lo);
            asm volatile("st.shared.b32 [%0], %1;" :: "r"(hbase + (uint32_t)(r * PADK + cc) * 2), "r"(hi) : "memory");
            asm volatile("st.shared.b32 [%0], %1;" :: "r"(hbase + MAT_BYTES + (uint32_t)(r * PADK + cc) * 2), "r"(lo) : "memory");
            split2(v10, v11, hi, lo);
            asm volatile("st.shared.b32 [%0], %1;" :: "r"(hbase + (uint32_t)((r + 8) * PADK + cc) * 2), "r"(hi) : "memory");
            asm volatile("st.shared.b32 [%0], %1;" :: "r"(hbase + MAT_BYTES + (uint32_t)((r + 8) * PADK + cc) * 2), "r"(lo) : "memory");
        }
    }

#pragma unroll
    for (int i = 0; i < 4; i++)
#pragma unroll
        for (int j = 0; j < 4; j++)
#pragma unroll
            for (int r = 0; r < 4; r++) acc[i][j][r] = 0.f;

    const uint32_t w2base = sb + 2 * STAGE_BYTES;
    for (int kc = 0; kc < 4; kc++) {
        {
            uint32_t d0 = (uint32_t)(lr0 * PADK + lc0) * 2;
            uint32_t d1 = (uint32_t)(lr1 * PADK + lc1) * 2;
            size_t gW0 = (size_t)lr0 * 128 + kc * 32 + lc0;
            size_t gW1 = (size_t)lr1 * 128 + kc * 32 + lc1;
            cp_async16(w2base + d0,             W2h + gW0);
            cp_async16(w2base + d1,             W2h + gW1);
            cp_async16(w2base + MAT_BYTES + d0, W2l + gW0);
            cp_async16(w2base + MAT_BYTES + d1, W2l + gW1);
        }
        cp_commit();
        cp_wait0();
        __syncthreads();

        const uint32_t hbase = sb + (uint32_t)kc * (2 * MAT_BYTES);
#pragma unroll
        for (int ks = 0; ks < 2; ks++) {
            const int k0 = ks * 16;
            uint32_t fah[4][4], fal[4][4], fbh[4][2], fbl[4][2];
            load_a_frags(hbase, hbase + MAT_BYTES, wm, lane, k0, fah, fal);
            load_b_frags(w2base, w2base + MAT_BYTES, wn, lane, k0, fbh, fbl);
            mma_block(acc, fah, fal, fbh, fbl);
        }
        __syncthreads();
    }

#pragma unroll
    for (int mi = 0; mi < 4; mi++) {
#pragma unroll
        for (int ni = 0; ni < 4; ni++) {
            int r0 = row0 + wm + mi * 16 + (lane >> 2);
            int c  = wn + ni * 8 + ((lane & 3) << 1);
            float b0 = b2[c], bb1 = b2[c + 1];
            *(float2*)&out[(size_t)r0 * 128 + c] =
                make_float2(acc[mi][ni][0] + b0, acc[mi][ni][1] + bb1);
            *(float2*)&out[(size_t)(r0 + 8) * 128 + c] =
                make_float2(acc[mi][ni][2] + b0, acc[mi][ni][3] + bb1);
        }
    }
}

// ---------------- MMA flash-attention, head-split -------------------------------
// Block = 128 threads / 4 warps; grid (N, B, 2); blockIdx.z = head-group hg.
// Warp w handles global head hg*4+w. Q/K/V head-group slices (64 cols) staged
// via cp.async from pre-split bf16 (no conversion) into 108 KB smem -> 2 CTAs/SM
// (one CTA's staging overlaps the other's MMA). Mainloop identical to R10.
#define ATT_PAD 72
#define ATT_MAT (128 * ATT_PAD * 2)    // 18432
#define ATT_SMEM (6 * ATT_MAT)         // 110592

__global__ __launch_bounds__(128, 2)
void attn_mma()
{
    extern __shared__ __align__(16) char smem[];
    const uint32_t sb = smem_u32(smem);

    const int n  = blockIdx.x;
    const int b  = blockIdx.y;
    const int hg = blockIdx.z;
    const int tid = threadIdx.x, lane = tid & 31, wid = tid >> 5;
    const int h_global = hg * 4 + wid;

    const size_t rowbase = (size_t)(b * 128) * 256 + n;    // global row of p=0

    // ---- stage Q,K,V head-group slices (64 cols) via cp.async ----
    {
        const __nv_bfloat16* srcs[6] = { g_q_hi, g_q_lo, g_k_hi, g_k_lo, g_v_hi, g_v_lo };
#pragma unroll
        for (int m = 0; m < 6; m++) {
            const uint16_t* __restrict__ src = (const uint16_t*)srcs[m] + hg * 64;
            uint32_t dstb = sb + (uint32_t)m * ATT_MAT;
#pragma unroll
            for (int j = 0; j < 8; j++) {
                int id  = tid + j * 128;      // 0..1023
                int row = id >> 3;            // p
                int c8  = (id & 7) * 8;       // col within slice
                cp_async16(dstb + (uint32_t)(row * ATT_PAD + c8) * 2,
                           src + (rowbase + (size_t)row * 256) * 128 + c8);
            }
        }
    }
    cp_commit();
    cp_wait0();
    __syncthreads();

    const uint32_t sqh = sb,                sql = sb + ATT_MAT;
    const uint32_t skh = sb + 2 * ATT_MAT,  skl = sb + 3 * ATT_MAT;
    const uint32_t svh = sb + 4 * ATT_MAT,  svl = sb + 5 * ATT_MAT;
    const uint32_t hoff = (uint32_t)wid * 32;   // head byte offset within slice row

    const int g  = lane >> 2;        // row within 8-row group
    const int tq = lane & 3;         // col pair index
    const float C = 0.36067376022224085f;    // log2(e) / sqrt(16)

#pragma unroll 1
    for (int mt = 0; mt < 8; mt++) {
        // Q fragments for rows mt*16..mt*16+15
        uint32_t qh[4], ql[4];
        {
            uint32_t off = (uint32_t)((mt * 16 + (lane & 15)) * ATT_PAD) * 2
                           + hoff + (uint32_t)((lane >> 4) << 4);
            ldmatrix_x4(qh, sqh + off);
            ldmatrix_x4(ql, sql + off);
        }

        float S[16][4];
        const int ntiles = 2 * mt + 2;
        for (int j = 0; j < ntiles; j++)
#pragma unroll
            for (int e = 0; e < 4; e++) S[j][e] = 0.f;

        // S = Q @ K^T over needed key tiles
        for (int jp = 0; jp <= mt; jp++) {
            uint32_t kh0[2], kh1[2], kl0[2], kl1[2];
            {
                uint32_t off = (uint32_t)((jp * 16 + ((lane >> 4) << 3) + (lane & 7)) * ATT_PAD) * 2
                               + hoff + (uint32_t)(((lane >> 3) & 1) << 4);
                uint32_t t[4];
                ldmatrix_x4(t, skh + off);
                kh0[0] = t[0]; kh0[1] = t[1]; kh1[0] = t[2]; kh1[1] = t[3];
                ldmatrix_x4(t, skl + off);
                kl0[0] = t[0]; kl0[1] = t[1]; kl1[0] = t[2]; kl1[1] = t[3];
            }
            mma_bf16(S[2*jp],   qh, kh0); mma_bf16(S[2*jp],   qh, kl0); mma_bf16(S[2*jp],   ql, kh0);
            mma_bf16(S[2*jp+1], qh, kh1); mma_bf16(S[2*jp+1], qh, kl1); mma_bf16(S[2*jp+1], ql, kh1);
        }

        // causal mask + row max
        const int p0 = mt * 16 + g, p1 = p0 + 8;
        float mx0 = -1e30f, mx1 = -1e30f;
        for (int j = 0; j < ntiles; j++) {
            int key0 = j * 8 + tq * 2, key1 = key0 + 1;
            if (key0 > p0) S[j][0] = -1e30f;
            if (key1 > p0) S[j][1] = -1e30f;
            if (key0 > p1) S[j][2] = -1e30f;
            if (key1 > p1) S[j][3] = -1e30f;
            mx0 = fmaxf(mx0, fmaxf(S[j][0], S[j][1]));
            mx1 = fmaxf(mx1, fmaxf(S[j][2], S[j][3]));
        }
        mx0 = fmaxf(mx0, __shfl_xor_sync(0xffffffffu, mx0, 1));
        mx0 = fmaxf(mx0, __shfl_xor_sync(0xffffffffu, mx0, 2));
        mx1 = fmaxf(mx1, __shfl_xor_sync(0xffffffffu, mx1, 1));
        mx1 = fmaxf(mx1, __shfl_xor_sync(0xffffffffu, mx1, 2));

        // exp + row sum (weights left unnormalized; normalize after PV)
        float sum0 = 0.f, sum1 = 0.f;
        for (int j = 0; j < ntiles; j++) {
            S[j][0] = ex2f((S[j][0] - mx0) * C);
            S[j][1] = ex2f((S[j][1] - mx0) * C);
            S[j][2] = ex2f((S[j][2] - mx1) * C);
            S[j][3] = ex2f((S[j][3] - mx1) * C);
            sum0 += S[j][0] + S[j][1];
            sum1 += S[j][2] + S[j][3];
        }
        sum0 += __shfl_xor_sync(0xffffffffu, sum0, 1);
        sum0 += __shfl_xor_sync(0xffffffffu, sum0, 2);
        sum1 += __shfl_xor_sync(0xffffffffu, sum1, 1);
        sum1 += __shfl_xor_sync(0xffffffffu, sum1, 2);

        // PV: attended[16 x 16] = P @ V
        float o0[4] = {0.f, 0.f, 0.f, 0.f};
        float o1[4] = {0.f, 0.f, 0.f, 0.f};
        for (int c = 0; c <= mt; c++) {
            uint32_t vh0[2], vh1[2], vl0[2], vl1[2];
            {
                uint32_t off = (uint32_t)((c * 16 + (((lane >> 3) & 1) << 3) + (lane & 7)) * ATT_PAD) * 2
                               + hoff + (uint32_t)((lane >> 4) << 4);
                uint32_t t[4];
                ldmatrix_x4t(t, svh + off);
                vh0[0] = t[0]; vh0[1] = t[1]; vh1[0] = t[2]; vh1[1] = t[3];
                ldmatrix_x4t(t, svl + off);
                vl0[0] = t[0]; vl0[1] = t[1]; vl1[0] = t[2]; vl1[1] = t[3];
            }
            // P A-frags straight from S accumulators (split)
            uint32_t ph[4], pl[4];
            split2(S[2*c][0],   S[2*c][1],   ph[0], pl[0]);
            split2(S[2*c][2],   S[2*c][3],   ph[1], pl[1]);
            split2(S[2*c+1][0], S[2*c+1][1], ph[2], pl[2]);
            split2(S[2*c+1][2], S[2*c+1][3], ph[3], pl[3]);

            mma_bf16(o0, ph, vh0); mma_bf16(o0, ph, vl0); mma_bf16(o0, pl, vh0);
            mma_bf16(o1, ph, vh1); mma_bf16(o1, ph, vl1); mma_bf16(o1, pl, vh1);
        }

        // normalize + write split bf16 to g_att
        const float inv0 = 1.f / sum0, inv1 = 1.f / sum1;
        const size_t r0b = (rowbase + (size_t)p0 * 256) * 128 + h_global * 16 + tq * 2;
        const size_t r1b = (rowbase + (size_t)p1 * 256) * 128 + h_global * 16 + tq * 2;
        uint32_t hi, lo;
        split2(o0[0] * inv0, o0[1] * inv0, hi, lo);
        *(uint32_t*)((uint16_t*)g_att_hi + r0b) = hi;
        *(uint32_t*)((uint16_t*)g_att_lo + r0b) = lo;
        split2(o0[2] * inv1, o0[3] * inv1, hi, lo);
        *(uint32_t*)((uint16_t*)g_att_hi + r1b) = hi;
        *(uint32_t*)((uint16_t*)g_att_lo + r1b) = lo;
        split2(o1[0] * inv0, o1[1] * inv0, hi, lo);
        *(uint32_t*)((uint16_t*)g_att_hi + r0b + 8) = hi;
        *(uint32_t*)((uint16_t*)g_att_lo + r0b + 8) = lo;
        split2(o1[2] * inv1, o1[3] * inv1, hi, lo);
        *(uint32_t*)((uint16_t*)g_att_hi + r1b + 8) = hi;
        *(uint32_t*)((uint16_t*)g_att_lo + r1b + 8) = lo;
    }
}

// ---------------- launch -------------------------------------------------------
extern "C" void kernel_launch(void* const* d_in, const int* in_sizes, int n_in,
                              void* d_out, int out_size)
{
    const float* X   = (const float*)d_in[0];
    const float* STE = (const float*)d_in[1];
    const float* Wq  = (const float*)d_in[2];
    const float* bq  = (const float*)d_in[3];
    const float* Wk  = (const float*)d_in[4];
    const float* bk  = (const float*)d_in[5];
    const float* Wv  = (const float*)d_in[6];
    const float* bv  = (const float*)d_in[7];
    const float* W1  = (const float*)d_in[8];
    const float* b1  = (const float*)d_in[9];
    const float* W2  = (const float*)d_in[10];
    const float* b2  = (const float*)d_in[11];
    float* out = (float*)d_out;

    cudaFuncSetAttribute(qkv_gemm,  cudaFuncAttributeMaxDynamicSharedMemorySize, QKV_SMEM);
    cudaFuncSetAttribute(mlp_fused, cudaFuncAttributeMaxDynamicSharedMemorySize, MLP_SMEM);
    cudaFuncSetAttribute(attn_mma,  cudaFuncAttributeMaxDynamicSharedMemorySize, ATT_SMEM);

    // preprocessing: weight transpose+split, activation concat+split
    convert_w<<<512, 256>>>(Wq, Wk, Wv, W1, W2);
    convert_a<<<32768, 256>>>(X, STE);

    // fused QKV projections (x = weight select -> L2-shared A tiles), split-bf16 out
    qkv_gemm<<<dim3(3, M_ / 128), 256, QKV_SMEM>>>(bq, bk, bv);

    // MMA flash-attention: block per (n, b, head-group), warp per head
    attn_mma<<<dim3(N_, B_, 2), 128, ATT_SMEM>>>();

    // fused output MLP
    mlp_fused<<<M_ / 128, 256, MLP_SMEM>>>(b1, b2, out);
}

// round 12
// speedup vs baseline: 1.1149x; 1.0812x over previous
#include <cuda_runtime.h>
#include <cuda_bf16.h>
#include <math.h>
#include <stdint.h>

#define B_   8
#define P_   128
#define N_   256
#define D_   128
#define M_   (B_*P_*N_)        // 262144 rows
#define ROWSTRIDE_ 32768       // N_*D_ elements between consecutive p for fixed (b,n)

// ---------------- scratch (device globals; no allocation allowed) ----------------
__device__ __align__(16) __nv_bfloat16 g_a_hi[(size_t)M_ * 256];
__device__ __align__(16) __nv_bfloat16 g_a_lo[(size_t)M_ * 256];
__device__ __align__(16) __nv_bfloat16 g_q_hi[(size_t)M_ * D_];
__device__ __align__(16) __nv_bfloat16 g_q_lo[(size_t)M_ * D_];
__device__ __align__(16) __nv_bfloat16 g_k_hi[(size_t)M_ * D_];
__device__ __align__(16) __nv_bfloat16 g_k_lo[(size_t)M_ * D_];
__device__ __align__(16) __nv_bfloat16 g_v_hi[(size_t)M_ * D_];
__device__ __align__(16) __nv_bfloat16 g_v_lo[(size_t)M_ * D_];
__device__ __align__(16) __nv_bfloat16 g_att_hi[(size_t)M_ * D_];
__device__ __align__(16) __nv_bfloat16 g_att_lo[(size_t)M_ * D_];
// weights transposed to [n][k], bf16-split. layout: Wq(32768) Wk Wv W1(16384) W2
__device__ __align__(16) __nv_bfloat16 g_wh[131072];
__device__ __align__(16) __nv_bfloat16 g_wl[131072];

// ---------------- helpers ----------------
__device__ __forceinline__ uint32_t smem_u32(const void* p) {
    uint32_t a;
    asm("{ .reg .u64 t; cvta.to.shared.u64 t, %1; cvt.u32.u64 %0, t; }" : "=r"(a) : "l"(p));
    return a;
}
__device__ __forceinline__ void split_bf16(float x, uint16_t& h, uint16_t& l) {
    __nv_bfloat16 hb = __float2bfloat16(x);
    __nv_bfloat16 lb = __float2bfloat16(x - __bfloat162float(hb));
    h = __bfloat16_as_ushort(hb);
    l = __bfloat16_as_ushort(lb);
}
__device__ __forceinline__ void split2(float a, float b, uint32_t& hi, uint32_t& lo) {
    uint16_t ha, la, hb, lb;
    split_bf16(a, ha, la);
    split_bf16(b, hb, lb);
    hi = (uint32_t)ha | ((uint32_t)hb << 16);
    lo = (uint32_t)la | ((uint32_t)lb << 16);
}
// exact bf16(hi)+bf16(lo) -> fp32 reconstruction
__device__ __forceinline__ float join_bf16(uint16_t h, uint16_t l) {
    return __uint_as_float((uint32_t)h << 16) + __uint_as_float((uint32_t)l << 16);
}
__device__ __forceinline__ void ldmatrix_x4(uint32_t* r, uint32_t addr) {
    asm volatile("ldmatrix.sync.aligned.m8n8.x4.shared.b16 {%0,%1,%2,%3}, [%4];"
                 : "=r"(r[0]), "=r"(r[1]), "=r"(r[2]), "=r"(r[3]) : "r"(addr));
}
__device__ __forceinline__ void mma_bf16(float* d, const uint32_t* a, const uint32_t* b) {
    asm volatile(
        "mma.sync.aligned.m16n8k16.row.col.f32.bf16.bf16.f32 "
        "{%0,%1,%2,%3}, {%4,%5,%6,%7}, {%8,%9}, {%0,%1,%2,%3};"
        : "+f"(d[0]), "+f"(d[1]), "+f"(d[2]), "+f"(d[3])
        : "r"(a[0]), "r"(a[1]), "r"(a[2]), "r"(a[3]), "r"(b[0]), "r"(b[1]));
}
__device__ __forceinline__ void cp_async16(uint32_t dst, const void* src) {
    asm volatile("cp.async.cg.shared.global [%0], [%1], 16;" :: "r"(dst), "l"(src));
}
__device__ __forceinline__ void cp_commit() {
    asm volatile("cp.async.commit_group;" ::: "memory");
}
__device__ __forceinline__ void cp_wait0() {
    asm volatile("cp.async.wait_group 0;" ::: "memory");
}

// ---------------- convert weights: W[k][n] fp32 -> transposed split bf16 ----------
__global__ void convert_w(const float* __restrict__ Wq, const float* __restrict__ Wk,
                          const float* __restrict__ Wv, const float* __restrict__ W1,
                          const float* __restrict__ W2)
{
    int id = blockIdx.x * 256 + threadIdx.x;      // < 131072
    const float* src; int K, n, k; size_t dofs;
    if (id < 98304) {
        int wi = id >> 15, rem = id & 32767;
        k = rem >> 7; n = rem & 127; K = 256;
        src = (wi == 0) ? Wq : (wi == 1) ? Wk : Wv;
        dofs = (size_t)wi * 32768;
    } else {
        int r2 = id - 98304;
        int wi = r2 >> 14, rem = r2 & 16383;
        k = rem >> 7; n = rem & 127; K = 128;
        src = wi ? W2 : W1;
        dofs = 98304 + (size_t)wi * 16384;
    }
    float x = src[(size_t)k * 128 + n];
    uint16_t h, l;
    split_bf16(x, h, l);
    size_t d = dofs + (size_t)n * K + k;
    ((uint16_t*)g_wh)[d] = h;
    ((uint16_t*)g_wl)[d] = l;
}

// ---------------- convert activations: concat(X,STE) -> split bf16 [M x 256] -----
__global__ void convert_a(const float* __restrict__ X, const float* __restrict__ STE)
{
    size_t id = (size_t)blockIdx.x * 256 + threadIdx.x;   // one per 8 elements
    int row = (int)(id >> 5);
    int c8  = (int)(id & 31) << 3;
    const float* src = (c8 < 128) ? (X + (size_t)row * 128 + c8)
                                  : (STE + (size_t)row * 128 + (c8 - 128));
    float4 v0 = ((const float4*)src)[0];
    float4 v1 = ((const float4*)src)[1];
    float vv[8] = {v0.x, v0.y, v0.z, v0.w, v1.x, v1.y, v1.z, v1.w};
    uint32_t hp[4], lp[4];
#pragma unroll
    for (int j = 0; j < 4; j++)
        split2(vv[2 * j], vv[2 * j + 1], hp[j], lp[j]);
    size_t e = (size_t)row * 256 + c8;
    *(uint4*)((uint16_t*)g_a_hi + e) = make_uint4(hp[0], hp[1], hp[2], hp[3]);
    *(uint4*)((uint16_t*)g_a_lo + e) = make_uint4(lp[0], lp[1], lp[2], lp[3]);
}

// ---------------- shared GEMM tile constants ------------------------------------
#define PADK 40                       // 80B row stride: 16B-aligned, ldmatrix conflict-free
#define MAT_BYTES (128 * PADK * 2)    // 10240
#define STAGE_BYTES (4 * MAT_BYTES)   // 40960
#define OFF_AH 0
#define OFF_AL MAT_BYTES
#define OFF_WH (2 * MAT_BYTES)
#define OFF_WL (3 * MAT_BYTES)
#define QKV_SMEM (2 * STAGE_BYTES)            // 81920
#define MLP_SMEM (2 * STAGE_BYTES + 20480)    // 102400

__device__ __forceinline__ void load_a_frags(uint32_t base_h, uint32_t base_l,
                                             int wm, int lane, int k0,
                                             uint32_t fah[4][4], uint32_t fal[4][4]) {
#pragma unroll
    for (int mi = 0; mi < 4; mi++) {
        uint32_t off = (uint32_t)((wm + mi * 16 + (lane & 15)) * PADK
                                  + k0 + ((lane >> 4) << 3)) * 2;
        ldmatrix_x4(fah[mi], base_h + off);
        ldmatrix_x4(fal[mi], base_l + off);
    }
}
__device__ __forceinline__ void load_b_frags(uint32_t base_h, uint32_t base_l,
                                             int wn, int lane, int k0,
                                             uint32_t fbh[4][2], uint32_t fbl[4][2]) {
#pragma unroll
    for (int njp = 0; njp < 2; njp++) {
        uint32_t off = (uint32_t)((wn + njp * 16 + ((lane >> 4) << 3) + (lane & 7)) * PADK
                                  + k0 + (((lane >> 3) & 1) << 3)) * 2;
        uint32_t t[4];
        ldmatrix_x4(t, base_h + off);
        fbh[2*njp][0] = t[0]; fbh[2*njp][1] = t[1];
        fbh[2*njp+1][0] = t[2]; fbh[2*njp+1][1] = t[3];
        ldmatrix_x4(t, base_l + off);
        fbl[2*njp][0] = t[0]; fbl[2*njp][1] = t[1];
        fbl[2*njp+1][0] = t[2]; fbl[2*njp+1][1] = t[3];
    }
}
__device__ __forceinline__ void mma_block(float acc[4][4][4],
                                          uint32_t fah[4][4], uint32_t fal[4][4],
                                          uint32_t fbh[4][2], uint32_t fbl[4][2]) {
#pragma unroll
    for (int mi = 0; mi < 4; mi++)
#pragma unroll
        for (int ni = 0; ni < 4; ni++) {
            mma_bf16(acc[mi][ni], fah[mi], fbh[ni]);
            mma_bf16(acc[mi][ni], fah[mi], fbl[ni]);
            mma_bf16(acc[mi][ni], fal[mi], fbh[ni]);
        }
}

// ---------------- fused QKV GEMM (split-bf16 epilogue, from R11) ------------------
__global__ __launch_bounds__(256)
void qkv_gemm(const float* __restrict__ bq, const float* __restrict__ bk,
              const float* __restrict__ bv)
{
    extern __shared__ __align__(16) char smem[];
    const uint32_t sb = smem_u32(smem);

    const int wsel = blockIdx.x;
    const int row0 = blockIdx.y * 128;
    const __nv_bfloat16* __restrict__ Ah = g_a_hi;
    const __nv_bfloat16* __restrict__ Al = g_a_lo;
    const __nv_bfloat16* __restrict__ Wh = g_wh + wsel * 32768;
    const __nv_bfloat16* __restrict__ Wl = g_wl + wsel * 32768;
    const float* __restrict__ bias = (wsel == 0) ? bq : (wsel == 1) ? bk : bv;
    uint16_t* __restrict__ oh = (uint16_t*)((wsel == 0) ? g_q_hi : (wsel == 1) ? g_k_hi : g_v_hi);
    uint16_t* __restrict__ ol = (uint16_t*)((wsel == 0) ? g_q_lo : (wsel == 1) ? g_k_lo : g_v_lo);

    const int tid  = threadIdx.x;
    const int lane = tid & 31;
    const int wid  = tid >> 5;
    const int wm   = (wid & 1) * 64;
    const int wn   = (wid >> 1) * 32;

    float acc[4][4][4];
#pragma unroll
    for (int i = 0; i < 4; i++)
#pragma unroll
        for (int j = 0; j < 4; j++)
#pragma unroll
            for (int r = 0; r < 4; r++) acc[i][j][r] = 0.f;

    const int c0 = tid * 2;
    const int lr0 = c0 >> 2,        lc0 = (c0 & 3) << 3;
    const int lr1 = (c0 + 1) >> 2,  lc1 = ((c0 + 1) & 3) << 3;

    auto load_stage = [&](int kt, int buf) {
        uint32_t s = sb + buf * STAGE_BYTES;
        uint32_t d0 = (uint32_t)(lr0 * PADK + lc0) * 2;
        uint32_t d1 = (uint32_t)(lr1 * PADK + lc1) * 2;
        size_t gA0 = (size_t)(row0 + lr0) * 256 + kt + lc0;
        size_t gA1 = (size_t)(row0 + lr1) * 256 + kt + lc1;
        size_t gW0 = (size_t)lr0 * 256 + kt + lc0;
        size_t gW1 = (size_t)lr1 * 256 + kt + lc1;
        cp_async16(s + OFF_AH + d0, Ah + gA0);
        cp_async16(s + OFF_AH + d1, Ah + gA1);
        cp_async16(s + OFF_AL + d0, Al + gA0);
        cp_async16(s + OFF_AL + d1, Al + gA1);
        cp_async16(s + OFF_WH + d0, Wh + gW0);
        cp_async16(s + OFF_WH + d1, Wh + gW1);
        cp_async16(s + OFF_WL + d0, Wl + gW0);
        cp_async16(s + OFF_WL + d1, Wl + gW1);
    };

    const int NS = 8;
    load_stage(0, 0);
    cp_commit();

    for (int s = 0; s < NS; s++) {
        cp_wait0();
        __syncthreads();
        if (s + 1 < NS) { load_stage((s + 1) * 32, (s + 1) & 1); cp_commit(); }

        const uint32_t base = sb + (s & 1) * STAGE_BYTES;
#pragma unroll
        for (int ks = 0; ks < 2; ks++) {
            const int k0 = ks * 16;
            uint32_t fah[4][4], fal[4][4], fbh[4][2], fbl[4][2];
            load_a_frags(base + OFF_AH, base + OFF_AL, wm, lane, k0, fah, fal);
            load_b_frags(base + OFF_WH, base + OFF_WL, wn, lane, k0, fbh, fbl);
            mma_block(acc, fah, fal, fbh, fbl);
        }
    }

#pragma unroll
    for (int mi = 0; mi < 4; mi++) {
#pragma unroll
        for (int ni = 0; ni < 4; ni++) {
            int r0 = row0 + wm + mi * 16 + (lane >> 2);
            int c  = wn + ni * 8 + ((lane & 3) << 1);
            float b0 = bias[c], b1 = bias[c + 1];
            float v00 = fmaxf(acc[mi][ni][0] + b0, 0.f), v01 = fmaxf(acc[mi][ni][1] + b1, 0.f);
            float v10 = fmaxf(acc[mi][ni][2] + b0, 0.f), v11 = fmaxf(acc[mi][ni][3] + b1, 0.f);
            uint32_t hi, lo;
            split2(v00, v01, hi, lo);
            *(uint32_t*)(oh + (size_t)r0 * 128 + c) = hi;
            *(uint32_t*)(ol + (size_t)r0 * 128 + c) = lo;
            split2(v10, v11, hi, lo);
            *(uint32_t*)(oh + (size_t)(r0 + 8) * 128 + c) = hi;
            *(uint32_t*)(ol + (size_t)(r0 + 8) * 128 + c) = lo;
        }
    }
}

// ---------------- fused MLP (unchanged from R9/R11) -------------------------------
__global__ __launch_bounds__(256)
void mlp_fused(const float* __restrict__ b1, const float* __restrict__ b2,
               float* __restrict__ out)
{
    extern __shared__ __align__(16) char smem[];
    const uint32_t sb = smem_u32(smem);

    const __nv_bfloat16* __restrict__ Ah = g_att_hi;
    const __nv_bfloat16* __restrict__ Al = g_att_lo;
    const __nv_bfloat16* __restrict__ W1h = g_wh + 98304;
    const __nv_bfloat16* __restrict__ W1l = g_wl + 98304;
    const __nv_bfloat16* __restrict__ W2h = g_wh + 114688;
    const __nv_bfloat16* __restrict__ W2l = g_wl + 114688;

    const int tid  = threadIdx.x;
    const int lane = tid & 31;
    const int wid  = tid >> 5;
    const int wm   = (wid & 1) * 64;
    const int wn   = (wid >> 1) * 32;
    const int row0 = blockIdx.x * 128;

    const int c0 = tid * 2;
    const int lr0 = c0 >> 2,        lc0 = (c0 & 3) << 3;
    const int lr1 = (c0 + 1) >> 2,  lc1 = ((c0 + 1) & 3) << 3;

    float acc[4][4][4];
#pragma unroll
    for (int i = 0; i < 4; i++)
#pragma unroll
        for (int j = 0; j < 4; j++)
#pragma unroll
            for (int r = 0; r < 4; r++) acc[i][j][r] = 0.f;

    auto load_stage1 = [&](int kt, int buf) {
        uint32_t s = sb + buf * STAGE_BYTES;
        uint32_t d0 = (uint32_t)(lr0 * PADK + lc0) * 2;
        uint32_t d1 = (uint32_t)(lr1 * PADK + lc1) * 2;
        size_t gA0 = (size_t)(row0 + lr0) * 128 + kt + lc0;
        size_t gA1 = (size_t)(row0 + lr1) * 128 + kt + lc1;
        size_t gW0 = (size_t)lr0 * 128 + kt + lc0;
        size_t gW1 = (size_t)lr1 * 128 + kt + lc1;
        cp_async16(s + OFF_AH + d0, Ah + gA0);
        cp_async16(s + OFF_AH + d1, Ah + gA1);
        cp_async16(s + OFF_AL + d0, Al + gA0);
        cp_async16(s + OFF_AL + d1, Al + gA1);
        cp_async16(s + OFF_WH + d0, W1h + gW0);
        cp_async16(s + OFF_WH + d1, W1h + gW1);
        cp_async16(s + OFF_WL + d0, W1l + gW0);
        cp_async16(s + OFF_WL + d1, W1l + gW1);
    };

    load_stage1(0, 0);
    cp_commit();
    for (int s = 0; s < 4; s++) {
        cp_wait0();
        __syncthreads();
        if (s + 1 < 4) { load_stage1((s + 1) * 32, (s + 1) & 1); cp_commit(); }
        const uint32_t base = sb + (s & 1) * STAGE_BYTES;
#pragma unroll
        for (int ks = 0; ks < 2; ks++) {
            const int k0 = ks * 16;
            uint32_t fah[4][4], fal[4][4], fbh[4][2], fbl[4][2];
            load_a_frags(base + OFF_AH, base + OFF_AL, wm, lane, k0, fah, fal);
            load_b_frags(base + OFF_WH, base + OFF_WL, wn, lane, k0, fbh, fbl);
            mma_block(acc, fah, fal, fbh, fbl);
        }
    }
    __syncthreads();

#pragma unroll
    for (int mi = 0; mi < 4; mi++) {
#pragma unroll
        for (int ni = 0; ni < 4; ni++) {
            int r  = wm + mi * 16 + (lane >> 2);
            int c  = wn + ni * 8 + ((lane & 3) << 1);
            int kc = c >> 5, cc = c & 31;
            uint32_t hbase = sb + (uint32_t)kc * (2 * MAT_BYTES);
            float b0 = b1[c], bb1 = b1[c + 1];
            float v00 = fmaxf(acc[mi][ni][0] + b0, 0.f), v01 = fmaxf(acc[mi][ni][1] + bb1, 0.f);
            float v10 = fmaxf(acc[mi][ni][2] + b0, 0.f), v11 = fmaxf(acc[mi][ni][3] + bb1, 0.f);
            uint32_t hi, lo;
            split2(v00, v01, hi, lo);
            asm volatile("st.shared.b32 [%0], %1;" :: "r"(hbase + (uint32_t)(r * PADK + cc) * 2), "r"(hi) : "memory");
            asm volatile("st.shared.b32 [%0], %1;" :: "r"(hbase + MAT_BYTES + (uint32_t)(r * PADK + cc) * 2), "r"(lo) : "memory");
            split2(v10, v11, hi, lo);
            asm volatile("st.shared.b32 [%0], %1;" :: "r"(hbase + (uint32_t)((r + 8) * PADK + cc) * 2), "r"(hi) : "memory");
            asm volatile("st.shared.b32 [%0], %1;" :: "r"(hbase + MAT_BYTES + (uint32_t)((r + 8) * PADK + cc) * 2), "r"(lo) : "memory");
        }
    }

#pragma unroll
    for (int i = 0; i < 4; i++)
#pragma unroll
        for (int j = 0; j < 4; j++)
#pragma unroll
            for (int r = 0; r < 4; r++) acc[i][j][r] = 0.f;

    const uint32_t w2base = sb + 2 * STAGE_BYTES;
    for (int kc = 0; kc < 4; kc++) {
        {
            uint32_t d0 = (uint32_t)(lr0 * PADK + lc0) * 2;
            uint32_t d1 = (uint32_t)(lr1 * PADK + lc1) * 2;
            size_t gW0 = (size_t)lr0 * 128 + kc * 32 + lc0;
            size_t gW1 = (size_t)lr1 * 128 + kc * 32 + lc1;
            cp_async16(w2base + d0,             W2h + gW0);
            cp_async16(w2base + d1,             W2h + gW1);
            cp_async16(w2base + MAT_BYTES + d0, W2l + gW0);
            cp_async16(w2base + MAT_BYTES + d1, W2l + gW1);
        }
        cp_commit();
        cp_wait0();
        __syncthreads();

        const uint32_t hbase = sb + (uint32_t)kc * (2 * MAT_BYTES);
#pragma unroll
        for (int ks = 0; ks < 2; ks++) {
            const int k0 = ks * 16;
            uint32_t fah[4][4], fal[4][4], fbh[4][2], fbl[4][2];
            load_a_frags(hbase, hbase + MAT_BYTES, wm, lane, k0, fah, fal);
            load_b_frags(w2base, w2base + MAT_BYTES, wn, lane, k0, fbh, fbl);
            mma_block(acc, fah, fal, fbh, fbl);
        }
        __syncthreads();
    }

#pragma unroll
    for (int mi = 0; mi < 4; mi++) {
#pragma unroll
        for (int ni = 0; ni < 4; ni++) {
            int r0 = row0 + wm + mi * 16 + (lane >> 2);
            int c  = wn + ni * 8 + ((lane & 3) << 1);
            float b0 = b2[c], bb1 = b2[c + 1];
            *(float2*)&out[(size_t)r0 * 128 + c] =
                make_float2(acc[mi][ni][0] + b0, acc[mi][ni][1] + bb1);
            *(float2*)&out[(size_t)(r0 + 8) * 128 + c] =
                make_float2(acc[mi][ni][2] + b0, acc[mi][ni][3] + bb1);
        }
    }
}

// ---------------- split-K scalar attention ---------------------------------------
// Block per (b, head, node), 256 threads. Thread pair (2t, 2t+1) owns query row t:
// lane u processes keys q = u, u+2, ... <= t (parity split keeps Ks[q] loads as
// two disjoint-bank broadcasts), then the two partial softmax states are merged
// via shfl_xor(1). K/V staged fp32 in smem from pre-split bf16 (exact reconstruct).
__global__ __launch_bounds__(256)
void attn_scalar()
{
    const int n  = blockIdx.x;
    const int bh = blockIdx.y;
    const int b  = bh >> 3;
    const int h  = bh & 7;
    const int tid = threadIdx.x;
    const int t  = tid >> 1;          // query row
    const int u  = tid & 1;           // key-parity half

    __shared__ float Ks[128][16];
    __shared__ float Vs[128][16];

    // element offset of (b, p=0, n) at this head's slice
    const size_t base = ((size_t)(b * P_) * N_ + n) * D_ + h * 16;

    // ---- stage K/V: thread handles (row = tid>>1, col-half = tid&1) ----
    {
        int r = tid >> 1, cs = (tid & 1) * 8;
        size_t off = base + (size_t)r * ROWSTRIDE_ + cs;
        uint4 KH = *(const uint4*)((const uint16_t*)g_k_hi + off);
        uint4 KL = *(const uint4*)((const uint16_t*)g_k_lo + off);
        uint4 VH = *(const uint4*)((const uint16_t*)g_v_hi + off);
        uint4 VL = *(const uint4*)((const uint16_t*)g_v_lo + off);
        const uint16_t* kh = (const uint16_t*)&KH;
        const uint16_t* kl = (const uint16_t*)&KL;
        const uint16_t* vh = (const uint16_t*)&VH;
        const uint16_t* vl = (const uint16_t*)&VL;
        float kf[8], vf[8];
#pragma unroll
        for (int i = 0; i < 8; i++) {
            kf[i] = join_bf16(kh[i], kl[i]);
            vf[i] = join_bf16(vh[i], vl[i]);
        }
        *(float4*)&Ks[r][cs]     = make_float4(kf[0], kf[1], kf[2], kf[3]);
        *(float4*)&Ks[r][cs + 4] = make_float4(kf[4], kf[5], kf[6], kf[7]);
        *(float4*)&Vs[r][cs]     = make_float4(vf[0], vf[1], vf[2], vf[3]);
        *(float4*)&Vs[r][cs + 4] = make_float4(vf[4], vf[5], vf[6], vf[7]);
    }

    // ---- Q row t (both lanes of the pair load the full row) ----
    float qr[16];
    {
        size_t off = base + (size_t)t * ROWSTRIDE_;
        uint4 H0 = *(const uint4*)((const uint16_t*)g_q_hi + off);
        uint4 H1 = *(const uint4*)((const uint16_t*)g_q_hi + off + 8);
        uint4 L0 = *(const uint4*)((const uint16_t*)g_q_lo + off);
        uint4 L1 = *(const uint4*)((const uint16_t*)g_q_lo + off + 8);
        const uint16_t* h0 = (const uint16_t*)&H0;
        const uint16_t* h1 = (const uint16_t*)&H1;
        const uint16_t* l0 = (const uint16_t*)&L0;
        const uint16_t* l1 = (const uint16_t*)&L1;
#pragma unroll
        for (int i = 0; i < 8; i++) {
            qr[i]     = join_bf16(h0[i], l0[i]);
            qr[i + 8] = join_bf16(h1[i], l1[i]);
        }
    }
    __syncthreads();

    // ---- online softmax over keys of parity u ----
    float m = -1e30f, denom = 0.f;
    float o[16];
#pragma unroll
    for (int d = 0; d < 16; d++) o[d] = 0.f;

    for (int q = u; q <= t; q += 2) {
        float4 k0 = *(const float4*)&Ks[q][0];
        float4 k1 = *(const float4*)&Ks[q][4];
        float4 k2 = *(const float4*)&Ks[q][8];
        float4 k3 = *(const float4*)&Ks[q][12];
        float s = qr[0] * k0.x;
        s = fmaf(qr[1],  k0.y, s); s = fmaf(qr[2],  k0.z, s); s = fmaf(qr[3],  k0.w, s);
        s = fmaf(qr[4],  k1.x, s); s = fmaf(qr[5],  k1.y, s); s = fmaf(qr[6],  k1.z, s); s = fmaf(qr[7],  k1.w, s);
        s = fmaf(qr[8],  k2.x, s); s = fmaf(qr[9],  k2.y, s); s = fmaf(qr[10], k2.z, s); s = fmaf(qr[11], k2.w, s);
        s = fmaf(qr[12], k3.x, s); s = fmaf(qr[13], k3.y, s); s = fmaf(qr[14], k3.z, s); s = fmaf(qr[15], k3.w, s);
        s *= 0.25f;   // 1/sqrt(d_head=16)

        if (s > m) {
            float scale = __expf(m - s);
            denom *= scale;
#pragma unroll
            for (int d = 0; d < 16; d++) o[d] *= scale;
            m = s;
        }
        float w = __expf(s - m);
        denom += w;

        float4 v0 = *(const float4*)&Vs[q][0];
        float4 v1 = *(const float4*)&Vs[q][4];
        float4 v2 = *(const float4*)&Vs[q][8];
        float4 v3 = *(const float4*)&Vs[q][12];
        o[0]  = fmaf(w, v0.x, o[0]);  o[1]  = fmaf(w, v0.y, o[1]);
        o[2]  = fmaf(w, v0.z, o[2]);  o[3]  = fmaf(w, v0.w, o[3]);
        o[4]  = fmaf(w, v1.x, o[4]);  o[5]  = fmaf(w, v1.y, o[5]);
        o[6]  = fmaf(w, v1.z, o[6]);  o[7]  = fmaf(w, v1.w, o[7]);
        o[8]  = fmaf(w, v2.x, o[8]);  o[9]  = fmaf(w, v2.y, o[9]);
        o[10] = fmaf(w, v2.z, o[10]); o[11] = fmaf(w, v2.w, o[11]);
        o[12] = fmaf(w, v3.x, o[12]); o[13] = fmaf(w, v3.y, o[13]);
        o[14] = fmaf(w, v3.z, o[14]); o[15] = fmaf(w, v3.w, o[15]);
    }

    // ---- merge the two parity-halves (lane pair via shfl_xor 1) ----
    float m2 = __shfl_xor_sync(0xffffffffu, m, 1);
    float d2 = __shfl_xor_sync(0xffffffffu, denom, 1);
    float M  = fmaxf(m, m2);
    float sa = __expf(m - M);
    float sb_ = __expf(m2 - M);
    float D  = denom * sa + d2 * sb_;
    float inv = 1.f / D;

    float val[16];
#pragma unroll
    for (int d = 0; d < 16; d++) {
        float oo = __shfl_xor_sync(0xffffffffu, o[d], 1);
        val[d] = (o[d] * sa + oo * sb_) * inv;
    }

    if (u == 0) {
        size_t ob = base + (size_t)t * ROWSTRIDE_;
        uint32_t hp[8], lp[8];
#pragma unroll
        for (int j = 0; j < 8; j++)
            split2(val[2 * j], val[2 * j + 1], hp[j], lp[j]);
        *(uint4*)((uint16_t*)g_att_hi + ob)     = make_uint4(hp[0], hp[1], hp[2], hp[3]);
        *(uint4*)((uint16_t*)g_att_hi + ob + 8) = make_uint4(hp[4], hp[5], hp[6], hp[7]);
        *(uint4*)((uint16_t*)g_att_lo + ob)     = make_uint4(lp[0], lp[1], lp[2], lp[3]);
        *(uint4*)((uint16_t*)g_att_lo + ob + 8) = make_uint4(lp[4], lp[5], lp[6], lp[7]);
    }
}

// ---------------- launch -------------------------------------------------------
extern "C" void kernel_launch(void* const* d_in, const int* in_sizes, int n_in,
                              void* d_out, int out_size)
{
    const float* X   = (const float*)d_in[0];
    const float* STE = (const float*)d_in[1];
    const float* Wq  = (const float*)d_in[2];
    const float* bq  = (const float*)d_in[3];
    const float* Wk  = (const float*)d_in[4];
    const float* bk  = (const float*)d_in[5];
    const float* Wv  = (const float*)d_in[6];
    const float* bv  = (const float*)d_in[7];
    const float* W1  = (const float*)d_in[8];
    const float* b1  = (const float*)d_in[9];
    const float* W2  = (const float*)d_in[10];
    const float* b2  = (const float*)d_in[11];
    float* out = (float*)d_out;

    cudaFuncSetAttribute(qkv_gemm,  cudaFuncAttributeMaxDynamicSharedMemorySize, QKV_SMEM);
    cudaFuncSetAttribute(mlp_fused, cudaFuncAttributeMaxDynamicSharedMemorySize, MLP_SMEM);

    // preprocessing: weight transpose+split, activation concat+split
    convert_w<<<512, 256>>>(Wq, Wk, Wv, W1, W2);
    convert_a<<<32768, 256>>>(X, STE);

    // fused QKV projections (x = weight select -> L2-shared A tiles), split-bf16 out
    qkv_gemm<<<dim3(3, M_ / 128), 256, QKV_SMEM>>>(bq, bk, bv);

    // split-K scalar attention: block per (b, head, node)
    attn_scalar<<<dim3(N_, B_ * 8), 256>>>();

    // fused output MLP
    mlp_fused<<<M_ / 128, 256, MLP_SMEM>>>(b1, b2, out);
}